// round 14
// baseline (speedup 1.0000x reference)
#include <cuda_runtime.h>
#include <cuda_fp16.h>
#include <cstdint>

// ---------------- problem constants ----------------
#define K2     36864
#define MTOT   1024
#define NTOT   768
#define SPLITK 6
#define KS     (K2 / SPLITK)      // 6144 k per CTA
#define BM     128
#define BN     256
#define BK     64                 // fp16 k per pipeline stage (128B rows)
#define NIT    (KS / BK)          // 96

#define BATCH   64
#define T_IN    12
#define HORIZON 12

// ---------------- device scratch ----------------
__device__ float g_part[(size_t)SPLITK * MTOT * NTOT];    // [s][m][n]

// ---------------- SMEM layout ----------------
// per stage: A 16K | B 32K = 48K; 4 stages = 192K (both stored fp16)
#define OFF_A   0
#define OFF_B   16384
#define STAGE_BYTES 49152
#define SMEM_TOTAL (4 * STAGE_BYTES)   // 196608

// ---------------- helpers ----------------
static __device__ __forceinline__ void ldsm4(uint32_t (&r)[4], uint32_t addr) {
    asm volatile("ldmatrix.sync.aligned.m8n8.x4.shared.b16 {%0,%1,%2,%3}, [%4];"
                 : "=r"(r[0]), "=r"(r[1]), "=r"(r[2]), "=r"(r[3]) : "r"(addr));
}

static __device__ __forceinline__ void mma16816(float (&d)[4], const uint32_t (&a)[4],
                                                uint32_t b0, uint32_t b1) {
    asm volatile("mma.sync.aligned.m16n8k16.row.col.f32.f16.f16.f32 "
                 "{%0,%1,%2,%3}, {%4,%5,%6,%7}, {%8,%9}, {%0,%1,%2,%3};"
                 : "+f"(d[0]), "+f"(d[1]), "+f"(d[2]), "+f"(d[3])
                 : "r"(a[0]), "r"(a[1]), "r"(a[2]), "r"(a[3]), "r"(b0), "r"(b1));
}

static __device__ __forceinline__ uint32_t pack_h2(float lo, float hi) {
    uint32_t r;
    asm("cvt.rn.f16x2.f32 %0, %1, %2;" : "=r"(r) : "f"(hi), "f"(lo));
    return r;
}

// ---------------- staging: 8 LDG.128 fp32 -> 4 STS.128 fp16 -----------------
// A stage = 1024 16B-chunks (4/thread). B stage = 2048 chunks, halves of 1024.
static __device__ __forceinline__ void loadA_regs(float4 (&v)[8],
                                                  const float* __restrict__ pA, int tid) {
    #pragma unroll
    for (int i = 0; i < 4; i++) {
        const int idx = i * 256 + tid;
        const int row = idx >> 3, c = idx & 7;
        const float* src = pA + (size_t)row * K2 + c * 8;
        v[2 * i]     = *reinterpret_cast<const float4*>(src);
        v[2 * i + 1] = *reinterpret_cast<const float4*>(src + 4);
    }
}
static __device__ __forceinline__ void storeA_smem(const float4 (&v)[8],
                                                   uint32_t stb, int tid) {
    #pragma unroll
    for (int i = 0; i < 4; i++) {
        const int idx = i * 256 + tid;
        const int row = idx >> 3, c = idx & 7;
        const uint32_t r0 = pack_h2(v[2 * i].x,     v[2 * i].y);
        const uint32_t r1 = pack_h2(v[2 * i].z,     v[2 * i].w);
        const uint32_t r2 = pack_h2(v[2 * i + 1].x, v[2 * i + 1].y);
        const uint32_t r3 = pack_h2(v[2 * i + 1].z, v[2 * i + 1].w);
        const uint32_t dst = stb + OFF_A + (uint32_t)(row * 128 + ((c ^ (row & 7)) << 4));
        asm volatile("st.shared.v4.b32 [%0], {%1,%2,%3,%4};"
                     :: "r"(dst), "r"(r0), "r"(r1), "r"(r2), "r"(r3));
    }
}
static __device__ __forceinline__ void loadB_half(float4 (&v)[8],
                                                  const float* __restrict__ pB,
                                                  int tid, int half) {
    #pragma unroll
    for (int i = 0; i < 4; i++) {
        const int rem = (half * 4 + i) * 256 + tid;   // chunk index 0..2047
        const int row = rem >> 3, c = rem & 7;
        const float* src = pB + (size_t)row * K2 + c * 8;
        v[2 * i]     = *reinterpret_cast<const float4*>(src);
        v[2 * i + 1] = *reinterpret_cast<const float4*>(src + 4);
    }
}
static __device__ __forceinline__ void stsB_half(const float4 (&v)[8],
                                                 uint32_t stb, int tid, int half) {
    #pragma unroll
    for (int i = 0; i < 4; i++) {
        const int rem = (half * 4 + i) * 256 + tid;
        const int row = rem >> 3, c = rem & 7;
        const uint32_t r0 = pack_h2(v[2 * i].x,     v[2 * i].y);
        const uint32_t r1 = pack_h2(v[2 * i].z,     v[2 * i].w);
        const uint32_t r2 = pack_h2(v[2 * i + 1].x, v[2 * i + 1].y);
        const uint32_t r3 = pack_h2(v[2 * i + 1].z, v[2 * i + 1].w);
        const uint32_t dst = stb + OFF_B + (uint32_t)(row * 128 + ((c ^ (row & 7)) << 4));
        asm volatile("st.shared.v4.b32 [%0], {%1,%2,%3,%4};"
                     :: "r"(dst), "r"(r0), "r"(r1), "r"(r2), "r"(r3));
    }
}

// one k16 slice of the block tile (ldsm + 32 HMMA)
static __device__ __forceinline__ void compute_k16(
    uint32_t stb, int kk, int lc, int lr, int wm, int wn, float (&acc)[4][8][4])
{
    const int c = kk * 2 + lc;
    uint32_t aH[4][4], bH[4][4];
    #pragma unroll
    for (int f = 0; f < 4; f++) {
        const int row = wm + f * 16 + lr;
        ldsm4(aH[f], stb + OFF_A + (uint32_t)(row * 128 + ((c ^ (row & 7)) << 4)));
    }
    #pragma unroll
    for (int g = 0; g < 4; g++) {
        const int row = wn + g * 16 + lr;
        ldsm4(bH[g], stb + OFF_B + (uint32_t)(row * 128 + ((c ^ (row & 7)) << 4)));
    }
    #pragma unroll
    for (int f = 0; f < 4; f++)
        #pragma unroll
        for (int j = 0; j < 8; j++)
            mma16816(acc[f][j], aH[f], bH[j >> 1][j & 1], bH[j >> 1][(j & 1) + 2]);
}

// ---------------- kernel 1: split-K GEMM, fused A+B convert, 1 staging buf --
__global__ void __launch_bounds__(256, 1)
gemm_mma_kernel(const float* __restrict__ Afp32, const float* __restrict__ Bfp32)
{
    extern __shared__ char smem[];
    const uint32_t sb = (uint32_t)__cvta_generic_to_shared(smem);
    const int tid  = threadIdx.x;
    const int lane = tid & 31;
    const int wid  = tid >> 5;
    const int wm   = (wid >> 2) * 64;    // 2 row bands
    const int wn   = (wid & 3) * 64;     // 4 col bands
    const int bm = blockIdx.x, bn = blockIdx.y, s = blockIdx.z;

    const size_t kbase = (size_t)s * KS;
    const float* pA = Afp32 + (size_t)(bm * BM) * K2 + kbase;
    const float* pB = Bfp32 + (size_t)(bn * BN) * K2 + kbase;

    float acc[4][8][4];
    #pragma unroll
    for (int f = 0; f < 4; f++)
        #pragma unroll
        for (int j = 0; j < 8; j++)
            #pragma unroll
            for (int r = 0; r < 4; r++) acc[f][j][r] = 0.0f;

    // prologue: fill stages 0..2 (LDG fp32 -> cvt -> STS fp16 for A and B)
    #pragma unroll
    for (int j = 0; j < 3; j++) {
        const uint32_t stb = sb + (uint32_t)j * STAGE_BYTES;
        float4 v[8];
        loadA_regs(v, pA + j * BK, tid);      storeA_smem(v, stb, tid);
        loadB_half(v, pB + j * BK, tid, 0);   stsB_half(v, stb, tid, 0);
        loadB_half(v, pB + j * BK, tid, 1);   stsB_half(v, stb, tid, 1);
    }

    const int lr = lane & 15;     // ldmatrix row within 16
    const int lc = lane >> 4;     // ldmatrix k-half

    for (int it = 0; it < NIT; ++it) {
        const bool ld = (it + 3) < NIT;
        const float* pAs = pA + (size_t)(it + 3) * BK;
        const float* pBs = pB + (size_t)(it + 3) * BK;

        // SINGLE 32-reg staging buffer, reused 3x per iteration
        float4 sv[8];
        if (ld) loadB_half(sv, pBs, tid, 0);   // in flight across barrier + kk0

        __syncthreads();   // stage it fully written; buffer (it-1)%4 now dead

        const uint32_t stb = sb + (uint32_t)(it & 3) * STAGE_BYTES;
        const uint32_t wtb = sb + (uint32_t)((it + 3) & 3) * STAGE_BYTES;

        compute_k16(stb, 0, lc, lr, wm, wn, acc);

        if (ld) { stsB_half(sv, wtb, tid, 0); loadB_half(sv, pBs, tid, 1); }

        compute_k16(stb, 1, lc, lr, wm, wn, acc);
        compute_k16(stb, 2, lc, lr, wm, wn, acc);

        if (ld) { stsB_half(sv, wtb, tid, 1); loadA_regs(sv, pAs, tid); }

        compute_k16(stb, 3, lc, lr, wm, wn, acc);

        if (ld) storeA_smem(sv, wtb, tid);   // next top barrier provides visibility
    }

    // store partials: [s][m][n]
    float* base = g_part + ((size_t)s * MTOT + (size_t)bm * BM) * NTOT + bn * BN;
    #pragma unroll
    for (int f = 0; f < 4; f++) {
        const int r0 = wm + f * 16 + (lane >> 2);
        #pragma unroll
        for (int j = 0; j < 8; j++) {
            const int n0 = wn + j * 8 + (lane & 3) * 2;
            *reinterpret_cast<float2*>(&base[(size_t)r0 * NTOT + n0]) =
                make_float2(acc[f][j][0], acc[f][j][1]);
            *reinterpret_cast<float2*>(&base[(size_t)(r0 + 8) * NTOT + n0]) =
                make_float2(acc[f][j][2], acc[f][j][3]);
        }
    }
}

// ---------------- kernel 2: split-K reduce + bias + einsum (b-fixed) --------
__global__ void __launch_bounds__(256)
epilogue_kernel(const float* __restrict__ x_all,   // output [64][12][1024][64]
                const float* __restrict__ b_hyp,   // [768]
                float* __restrict__ out)           // [64][12][1024]
{
    __shared__ float4 sh_h4[HORIZON * 17];   // [t][16] pad 17
    __shared__ float4 sh_x4[BATCH * 17];     // [b][16] pad 17

    const int n   = blockIdx.x;
    const int tid = threadIdx.x;

    // h: 192 float4 (768 floats): split-K reduce + bias
    if (tid < 192) {
        float4 a = reinterpret_cast<const float4*>(b_hyp)[tid];
        #pragma unroll
        for (int sp = 0; sp < SPLITK; sp++) {
            float4 v = *reinterpret_cast<const float4*>(
                &g_part[((size_t)sp * MTOT + n) * NTOT + tid * 4]);
            a.x += v.x; a.y += v.y; a.z += v.z; a.w += v.w;
        }
        sh_h4[(tid >> 4) * 17 + (tid & 15)] = a;
    }

    // x: 1024 float4 (64 b x 16 fc)
    #pragma unroll
    for (int r = 0; r < 4; r++) {
        const int i = tid + 256 * r;
        const int b = i >> 4, fc = i & 15;
        sh_x4[b * 17 + fc] = *reinterpret_cast<const float4*>(
            &x_all[((size_t)(b * T_IN + (T_IN - 1)) * MTOT + n) * 64 + fc * 4]);
    }
    __syncthreads();

    // thread fixes b, computes 3 horizons: xv loaded once per fc
    const int b  = tid & 63;
    const int tg = tid >> 6;       // 0..3 -> t = 3*tg + {0,1,2}
    float a0 = 0.f, a1 = 0.f, a2 = 0.f;
    #pragma unroll
    for (int fc = 0; fc < 16; fc++) {
        const float4 xv = sh_x4[b * 17 + fc];
        const float4 h0 = sh_h4[(3 * tg + 0) * 17 + fc];
        const float4 h1 = sh_h4[(3 * tg + 1) * 17 + fc];
        const float4 h2 = sh_h4[(3 * tg + 2) * 17 + fc];
        a0 += xv.x * h0.x + xv.y * h0.y + xv.z * h0.z + xv.w * h0.w;
        a1 += xv.x * h1.x + xv.y * h1.y + xv.z * h1.z + xv.w * h1.w;
        a2 += xv.x * h2.x + xv.y * h2.y + xv.z * h2.z + xv.w * h2.w;
    }
    out[((size_t)b * HORIZON + 3 * tg + 0) * MTOT + n] = a0;
    out[((size_t)b * HORIZON + 3 * tg + 1) * MTOT + n] = a1;
    out[((size_t)b * HORIZON + 3 * tg + 2) * MTOT + n] = a2;
}

// ---------------- launch ----------------
extern "C" void kernel_launch(void* const* d_in, const int* in_sizes, int n_in,
                              void* d_out, int out_size) {
    const float* output  = (const float*)d_in[0];   // [64,12,1024,64]
    const float* weights = (const float*)d_in[1];   // [1024,36864]
    const float* W_hyp   = (const float*)d_in[2];   // [768,36864]
    const float* b_hyp   = (const float*)d_in[3];   // [768]
    float* out = (float*)d_out;

    cudaFuncSetAttribute(gemm_mma_kernel,
                         cudaFuncAttributeMaxDynamicSharedMemorySize, SMEM_TOTAL);

    dim3 grid(MTOT / BM, NTOT / BN, SPLITK);   // (8, 3, 6) = 144 CTAs
    gemm_mma_kernel<<<grid, 256, SMEM_TOTAL>>>(weights, W_hyp);

    epilogue_kernel<<<MTOT, 256>>>(output, b_hyp, out);
}

// round 15
// speedup vs baseline: 1.3543x; 1.3543x over previous
#include <cuda_runtime.h>
#include <cuda_fp16.h>
#include <cstdint>

// ---------------- problem constants ----------------
#define K2     36864
#define MTOT   1024
#define NTOT   768
#define SPLITK 6
#define KS     (K2 / SPLITK)      // 6144 k per CTA
#define BM     128
#define BN     256
#define BK     64                 // fp16 k per pipeline stage (128B rows)
#define NIT    (KS / BK)          // 96

#define BATCH   64
#define T_IN    12
#define HORIZON 12

// ---------------- device scratch ----------------
__device__ __half g_Bh[(size_t)NTOT * K2];                 // B rounded once to fp16
__device__ __half g_part[(size_t)SPLITK * MTOT * NTOT];    // fp16 partials [s][m][n]

// ---------------- SMEM layout ----------------
// per stage: A 16K | B 32K = 48K; 4 stages = 192K
#define OFF_A   0
#define OFF_B   16384
#define STAGE_BYTES 49152
#define SMEM_TOTAL (4 * STAGE_BYTES)   // 196608

// ---------------- helpers ----------------
static __device__ __forceinline__ void cpa16(uint32_t dst, const void* src) {
    asm volatile("cp.async.cg.shared.global [%0], [%1], 16;\n" :: "r"(dst), "l"(src));
}
static __device__ __forceinline__ void cp_commit() {
    asm volatile("cp.async.commit_group;\n" ::: "memory");
}

static __device__ __forceinline__ void ldsm4(uint32_t (&r)[4], uint32_t addr) {
    asm volatile("ldmatrix.sync.aligned.m8n8.x4.shared.b16 {%0,%1,%2,%3}, [%4];"
                 : "=r"(r[0]), "=r"(r[1]), "=r"(r[2]), "=r"(r[3]) : "r"(addr));
}

static __device__ __forceinline__ void mma16816(float (&d)[4], const uint32_t (&a)[4],
                                                uint32_t b0, uint32_t b1) {
    asm volatile("mma.sync.aligned.m16n8k16.row.col.f32.f16.f16.f32 "
                 "{%0,%1,%2,%3}, {%4,%5,%6,%7}, {%8,%9}, {%0,%1,%2,%3};"
                 : "+f"(d[0]), "+f"(d[1]), "+f"(d[2]), "+f"(d[3])
                 : "r"(a[0]), "r"(a[1]), "r"(a[2]), "r"(a[3]), "r"(b0), "r"(b1));
}

static __device__ __forceinline__ uint32_t pack_h2(float lo, float hi) {
    uint32_t r;
    asm("cvt.rn.f16x2.f32 %0, %1, %2;" : "=r"(r) : "f"(hi), "f"(lo));
    return r;
}

// ---------------- kernel 0: B fp32 -> fp16, coalesced, MLP=8 ---------------
__global__ void __launch_bounds__(256)
convertB_kernel(const float* __restrict__ src) {
    const size_t base = (size_t)blockIdx.x * 2048 + threadIdx.x;
    float4 v[8];
    #pragma unroll
    for (int k = 0; k < 8; k++)
        v[k] = reinterpret_cast<const float4*>(src)[base + k * 256];
    #pragma unroll
    for (int k = 0; k < 8; k++) {
        uint2 o;
        o.x = pack_h2(v[k].x, v[k].y);
        o.y = pack_h2(v[k].z, v[k].w);
        reinterpret_cast<uint2*>(g_Bh)[base + k * 256] = o;
    }
}

// ---------------- A loader pieces (fp32 LDG -> regs -> cvt -> STS) ----------
static __device__ __forceinline__ void loadA_regs(float4 (&av)[8],
                                                  const float* __restrict__ pA, int tid) {
    #pragma unroll
    for (int i = 0; i < 4; i++) {
        const int idx = i * 256 + tid;
        const int row = idx >> 3, c = idx & 7;
        const float* src = pA + (size_t)row * K2 + c * 8;
        av[2 * i]     = *reinterpret_cast<const float4*>(src);
        av[2 * i + 1] = *reinterpret_cast<const float4*>(src + 4);
    }
}
static __device__ __forceinline__ void storeA_smem(const float4 (&av)[8],
                                                   uint32_t stb, int tid) {
    #pragma unroll
    for (int i = 0; i < 4; i++) {
        const int idx = i * 256 + tid;
        const int row = idx >> 3, c = idx & 7;
        const uint32_t r0 = pack_h2(av[2 * i].x,     av[2 * i].y);
        const uint32_t r1 = pack_h2(av[2 * i].z,     av[2 * i].w);
        const uint32_t r2 = pack_h2(av[2 * i + 1].x, av[2 * i + 1].y);
        const uint32_t r3 = pack_h2(av[2 * i + 1].z, av[2 * i + 1].w);
        const uint32_t dst = stb + OFF_A + (uint32_t)(row * 128 + ((c ^ (row & 7)) << 4));
        asm volatile("st.shared.v4.b32 [%0], {%1,%2,%3,%4};"
                     :: "r"(dst), "r"(r0), "r"(r1), "r"(r2), "r"(r3));
    }
}

// B per stage: 2048 x 16B chunks via cp.async; 8/thread; one commit group per stage.
static __device__ __forceinline__ void loadB_stage(uint32_t stb,
                                                   const __half* __restrict__ pB, int tid) {
    #pragma unroll
    for (int i = 0; i < 8; i++) {
        const int rem = i * 256 + tid;
        const int row = rem >> 3, c = rem & 7;
        cpa16(stb + OFF_B + (uint32_t)(row * 128 + ((c ^ (row & 7)) << 4)),
              pB + (size_t)row * K2 + c * 8);
    }
    cp_commit();
}

// ---------------- kernel 1: split-K GEMM, fused A convert, 4-stage ----------
__global__ void __launch_bounds__(256, 1)
gemm_mma_kernel(const float* __restrict__ Afp32)
{
    extern __shared__ char smem[];
    const uint32_t sb = (uint32_t)__cvta_generic_to_shared(smem);
    const int tid  = threadIdx.x;
    const int lane = tid & 31;
    const int wid  = tid >> 5;
    const int wm   = (wid >> 2) * 64;    // 2 row bands
    const int wn   = (wid & 3) * 64;     // 4 col bands
    const int bm = blockIdx.x, bn = blockIdx.y, s = blockIdx.z;

    const size_t kbase = (size_t)s * KS;
    const float*  pA = Afp32 + (size_t)(bm * BM) * K2 + kbase;
    const __half* pB = g_Bh  + (size_t)(bn * BN) * K2 + kbase;

    float acc[4][8][4];
    #pragma unroll
    for (int f = 0; f < 4; f++)
        #pragma unroll
        for (int j = 0; j < 8; j++)
            #pragma unroll
            for (int r = 0; r < 4; r++) acc[f][j][r] = 0.0f;

    // prologue: stages 0..2 (B via 3 ordered commit groups; A direct LDG+STS)
    loadB_stage(sb,                   pB,          tid);
    loadB_stage(sb + STAGE_BYTES,     pB + BK,     tid);
    loadB_stage(sb + 2 * STAGE_BYTES, pB + 2 * BK, tid);
    {
        float4 av[8];
        loadA_regs(av, pA, tid);          storeA_smem(av, sb, tid);
        loadA_regs(av, pA + BK, tid);     storeA_smem(av, sb + STAGE_BYTES, tid);
        loadA_regs(av, pA + 2 * BK, tid); storeA_smem(av, sb + 2 * STAGE_BYTES, tid);
    }

    const int lr = lane & 15;     // ldmatrix row within 16
    const int lc = lane >> 4;     // ldmatrix k-half

    for (int it = 0; it < NIT; ++it) {
        const bool ld = (it + 3) < NIT;

        // A fp32 loads for stage it+3 (gmem->regs; consumed after compute)
        float4 av[8];
        if (ld) loadA_regs(av, pA + (size_t)(it + 3) * BK, tid);

        // B of stage it complete: outstanding groups = it, it+1, it+2 -> allow 2
        asm volatile("cp.async.wait_group 2;\n" ::: "memory");
        __syncthreads();   // single barrier per iteration

        const uint32_t stb = sb + (uint32_t)(it & 3) * STAGE_BYTES;
        const uint32_t wtb = sb + (uint32_t)((it + 3) & 3) * STAGE_BYTES;

        // issue next B stage NOW: buffer (it+3)%4 == (it-1)%4 is dead after the
        // barrier; cp.async gains a full compute block of overlap.
        if (ld) loadB_stage(wtb, pB + (size_t)(it + 3) * BK, tid);
        else    cp_commit();   // keep group accounting uniform

        #pragma unroll
        for (int kk = 0; kk < 4; kk++) {          // 4 x k16 per stage
            const int c = kk * 2 + lc;
            uint32_t aH[4][4], bH[4][4];
            #pragma unroll
            for (int f = 0; f < 4; f++) {
                const int row = wm + f * 16 + lr;
                ldsm4(aH[f], stb + OFF_A + (uint32_t)(row * 128 + ((c ^ (row & 7)) << 4)));
            }
            #pragma unroll
            for (int g = 0; g < 4; g++) {
                const int row = wn + g * 16 + lr;
                ldsm4(bH[g], stb + OFF_B + (uint32_t)(row * 128 + ((c ^ (row & 7)) << 4)));
            }
            #pragma unroll
            for (int f = 0; f < 4; f++)
                #pragma unroll
                for (int j = 0; j < 8; j++)
                    mma16816(acc[f][j], aH[f], bH[j >> 1][j & 1], bH[j >> 1][(j & 1) + 2]);
        }

        // A store tail: LDGs had the whole compute block to land; no trailing
        // barrier (next iteration's top barrier provides visibility).
        if (ld) storeA_smem(av, wtb, tid);
    }

    // store partials as fp16: [s][m][n]; n0 is even -> 4B-aligned packed stores
    __half* base = g_part + ((size_t)s * MTOT + (size_t)bm * BM) * NTOT + bn * BN;
    #pragma unroll
    for (int f = 0; f < 4; f++) {
        const int r0 = wm + f * 16 + (lane >> 2);
        #pragma unroll
        for (int j = 0; j < 8; j++) {
            const int n0 = wn + j * 8 + (lane & 3) * 2;
            *reinterpret_cast<uint32_t*>(&base[(size_t)r0 * NTOT + n0]) =
                pack_h2(acc[f][j][0], acc[f][j][1]);
            *reinterpret_cast<uint32_t*>(&base[(size_t)(r0 + 8) * NTOT + n0]) =
                pack_h2(acc[f][j][2], acc[f][j][3]);
        }
    }
}

// ---------------- kernel 2: split-K reduce (fp16) + bias + einsum -----------
__global__ void __launch_bounds__(256)
epilogue_kernel(const float* __restrict__ x_all,   // output [64][12][1024][64]
                const float* __restrict__ b_hyp,   // [768]
                float* __restrict__ out)           // [64][12][1024]
{
    __shared__ float4 sh_h4[HORIZON * 17];   // [t][16] pad 17
    __shared__ float4 sh_x4[BATCH * 17];     // [b][16] pad 17

    const int n   = blockIdx.x;
    const int tid = threadIdx.x;

    // h: 96 threads x 8 consecutive entries; fp16 partials read as uint4
    if (tid < 96) {
        const int j0 = tid * 8;
        float hacc[8];
        {
            float4 b0 = *reinterpret_cast<const float4*>(&b_hyp[j0]);
            float4 b1 = *reinterpret_cast<const float4*>(&b_hyp[j0 + 4]);
            hacc[0] = b0.x; hacc[1] = b0.y; hacc[2] = b0.z; hacc[3] = b0.w;
            hacc[4] = b1.x; hacc[5] = b1.y; hacc[6] = b1.z; hacc[7] = b1.w;
        }
        #pragma unroll
        for (int sp = 0; sp < SPLITK; sp++) {
            const uint4 v = *reinterpret_cast<const uint4*>(
                &g_part[((size_t)sp * MTOT + n) * NTOT + j0]);
            const uint32_t w[4] = {v.x, v.y, v.z, v.w};
            #pragma unroll
            for (int q = 0; q < 4; q++) {
                const float2 f2 = __half22float2(*reinterpret_cast<const __half2*>(&w[q]));
                hacc[2 * q]     += f2.x;
                hacc[2 * q + 1] += f2.y;
            }
        }
        const int t  = j0 >> 6;
        const int fc = (j0 & 63) >> 2;
        sh_h4[t * 17 + fc]     = make_float4(hacc[0], hacc[1], hacc[2], hacc[3]);
        sh_h4[t * 17 + fc + 1] = make_float4(hacc[4], hacc[5], hacc[6], hacc[7]);
    }

    // x: 1024 float4 (64 b x 16 fc)
    #pragma unroll
    for (int r = 0; r < 4; r++) {
        const int i = tid + 256 * r;
        const int b = i >> 4, fc = i & 15;
        sh_x4[b * 17 + fc] = *reinterpret_cast<const float4*>(
            &x_all[((size_t)(b * T_IN + (T_IN - 1)) * MTOT + n) * 64 + fc * 4]);
    }
    __syncthreads();

    // thread fixes b, computes 3 horizons: xv loaded once per fc
    const int b  = tid & 63;
    const int tg = tid >> 6;       // 0..3 -> t = 3*tg + {0,1,2}
    float a0 = 0.f, a1 = 0.f, a2 = 0.f;
    #pragma unroll
    for (int fc = 0; fc < 16; fc++) {
        const float4 xv = sh_x4[b * 17 + fc];
        const float4 h0 = sh_h4[(3 * tg + 0) * 17 + fc];
        const float4 h1 = sh_h4[(3 * tg + 1) * 17 + fc];
        const float4 h2 = sh_h4[(3 * tg + 2) * 17 + fc];
        a0 += xv.x * h0.x + xv.y * h0.y + xv.z * h0.z + xv.w * h0.w;
        a1 += xv.x * h1.x + xv.y * h1.y + xv.z * h1.z + xv.w * h1.w;
        a2 += xv.x * h2.x + xv.y * h2.y + xv.z * h2.z + xv.w * h2.w;
    }
    out[((size_t)b * HORIZON + 3 * tg + 0) * MTOT + n] = a0;
    out[((size_t)b * HORIZON + 3 * tg + 1) * MTOT + n] = a1;
    out[((size_t)b * HORIZON + 3 * tg + 2) * MTOT + n] = a2;
}

// ---------------- launch ----------------
extern "C" void kernel_launch(void* const* d_in, const int* in_sizes, int n_in,
                              void* d_out, int out_size) {
    const float* output  = (const float*)d_in[0];   // [64,12,1024,64]
    const float* weights = (const float*)d_in[1];   // [1024,36864]
    const float* W_hyp   = (const float*)d_in[2];   // [768,36864]
    const float* b_hyp   = (const float*)d_in[3];   // [768]
    float* out = (float*)d_out;

    cudaFuncSetAttribute(gemm_mma_kernel,
                         cudaFuncAttributeMaxDynamicSharedMemorySize, SMEM_TOTAL);

    const int nblk = NTOT * K2 / 2048 / 4;   // 3456 blocks x 2048 float4
    convertB_kernel<<<nblk, 256>>>(W_hyp);

    dim3 grid(MTOT / BM, NTOT / BN, SPLITK);   // (8, 3, 6) = 144 CTAs
    gemm_mma_kernel<<<grid, 256, SMEM_TOTAL>>>(weights);

    epilogue_kernel<<<MTOT, 256>>>(output, b_hyp, out);
}